// round 9
// baseline (speedup 1.0000x reference)
#include <cuda_runtime.h>
#include <cuda_fp16.h>
#include <cstdint>
#include <math.h>

// DenseHyperbolic: fused GEMM (mma.sync m16n8k16 fp16, Markidis fp16x3 split,
// fp32 accumulate) + analytic per-row hyperbolic epilogue.
//   g = v'(col0=0) @ W ; out_j = Aw*g_j + Ab*bias_j ; out_0 = sqrt(c2)*cosh(.)
//
// R8: tensor 56.5%, ~600cyc/chunk exposed (wait+barrier convoy, fragment head
// latency). R9: 3 W stages with lead-2 cp.async (steady-state wait_group 1 is
// a no-op), A fragments for chunk i+1 prefetched at the end of chunk i (A is
// smem-resident -> no hazard), 1-deep B fragment rotation. One bar.sync per
// chunk is the only remaining serial cost. 112KB/CTA, 2 CTAs/SM.

constexpr int D   = 256;
constexpr int BM  = 64;
constexpr int NCH = 16;            // chunks of K=16
constexpr int NT  = 256;
constexpr int A_BYTES  = 65536;    // 16 chunks x (hi 2KB + lo 2KB)
constexpr int WSTAGE_B = 16384;
constexpr int NSTG     = 3;
constexpr int SMEM_DYN = A_BYTES + NSTG * WSTAGE_B;   // 112 KB

#define EPSF       1e-4f
#define ACOSH_MINF 1.0001f
#define CLIPF      8.0f

// W image: [16 chunks][32 ngroups][4 tiles: hiK0|hiK1|loK0|loK1][64 halves]
__device__ __half w_img[16 * 8192];

__device__ __forceinline__ uint32_t smem_u32(const void* p) {
    uint32_t a;
    asm("{ .reg .u64 t; cvta.to.shared.u64 t, %1; cvt.u32.u64 %0, t; }"
        : "=r"(a) : "l"(p));
    return a;
}
__device__ __forceinline__ uint32_t packh(__half a, __half b) {
    __half2 h = __halves2half2(a, b);
    return *reinterpret_cast<uint32_t*>(&h);
}

#define MMAF16(C, A, b0, b1) \
    asm volatile("mma.sync.aligned.m16n8k16.row.col.f32.f16.f16.f32 " \
        "{%0,%1,%2,%3}, {%4,%5,%6,%7}, {%8,%9}, {%0,%1,%2,%3};" \
        : "+f"((C)[0]), "+f"((C)[1]), "+f"((C)[2]), "+f"((C)[3]) \
        : "r"((A)[0]), "r"((A)[1]), "r"((A)[2]), "r"((A)[3]), \
          "r"(b0), "r"(b1))

#define LDSM4(R, addr) \
    asm volatile("ldmatrix.sync.aligned.m8n8.x4.shared.b16 {%0,%1,%2,%3}, [%4];" \
        : "=r"((R)[0]), "=r"((R)[1]), "=r"((R)[2]), "=r"((R)[3]) : "r"(addr))

#define CP_ASYNC16(dst_u32, src_ptr) \
    asm volatile("cp.async.cg.shared.global [%0], [%1], 16;" \
                 :: "r"(dst_u32), "l"(src_ptr))
#define CP_COMMIT() asm volatile("cp.async.commit_group;")
#define CP_WAIT0()  asm volatile("cp.async.wait_group 0;" ::: "memory")
#define CP_WAIT1()  asm volatile("cp.async.wait_group 1;" ::: "memory")

// ---- prep: W[k][n] row-major -> fragment-tiled fp16 hi/lo image ----
__global__ void prep_w(const float* __restrict__ W) {
    int t = blockIdx.x * 256 + threadIdx.x;      // 8192 tasks
    int c  = t >> 9;                             // k16 chunk
    int rm = t & 511;
    int ng = rm >> 4;                            // n group (8 cols)
    int kt = (rm >> 3) & 1;
    int rr = rm & 7;                             // n within group
    int n  = ng * 8 + rr;
    int kb = c * 16 + kt * 8;
    __half h[8], l[8];
    #pragma unroll
    for (int j = 0; j < 8; ++j) {
        float v  = W[(size_t)(kb + j) * 256 + n];
        __half hi = __float2half_rn(v);
        h[j] = hi;
        l[j] = __float2half_rn(v - __half2float(hi));
    }
    size_t base = (size_t)c * 8192 + ng * 256 + kt * 64 + rr * 8;   // halves
    *reinterpret_cast<uint4*>(w_img + base)       = *reinterpret_cast<const uint4*>(h);
    *reinterpret_cast<uint4*>(w_img + base + 128) = *reinterpret_cast<const uint4*>(l);
}

// ---- main kernel ----
__global__ __launch_bounds__(NT, 2)
void dh_mma(const float* __restrict__ V,
            const float* __restrict__ cin_p,
            const float* __restrict__ cout_p,
            const float* __restrict__ bias,
            float* __restrict__ out)
{
    extern __shared__ __align__(16) char smc[];   // A 64KB | W stages 48KB
    const int tid  = threadIdx.x;
    const int lane = tid & 31;
    const int wid  = tid >> 5;
    const int wm   = wid >> 2;        // 0..1 (M)
    const int wn   = wid & 3;         // 0..3 (N)
    const int row0 = blockIdx.x * BM;
    const uint32_t smem0 = smem_u32(smc);

    // epilogue alias region (inside W stage 0; used only after mainloop)
    float* al     = reinterpret_cast<float*>(smc + A_BYTES);
    float* sbias  = al;               // 256
    float* sgp    = al + 256;         // 64 x 4
    float* sdgp   = al + 512;         // 64 x 4
    float* svsum  = al + 768;         // 64
    float* sAw    = al + 832;
    float* sAb    = al + 896;
    float* sO0    = al + 960;
    float* sred   = al + 1024;        // 8
    float* sSb    = al + 1032;

    // ---- W stage cp.async (16KB linear copy) ----
    auto cp_w = [&](int i, int stg) {
        const __half* src = w_img + (size_t)i * 8192;
        uint32_t dst = smem0 + A_BYTES + stg * WSTAGE_B;
        #pragma unroll
        for (int j = 0; j < 4; ++j) {
            int f = tid + j * 256;               // 16B units, 0..1023
            CP_ASYNC16(dst + f * 16, src + f * 8);
        }
        CP_COMMIT();
    };

    // lead-2 prologue: stages 0 and 1 in flight during the A conversion
    cp_w(0, 0);
    cp_w(1, 1);

    // ---- A prologue: convert 64x256 tile to hi/lo fp16, resident in smem ----
    const int lr = tid >> 2;
    const int q  = tid & 3;
    const uint32_t aStsOff = (uint32_t)(((lr >> 3) * 2 + (q >> 1)) * 128
                                        + (lr & 7) * 16 + (q & 1) * 8);
    float svloc = 0.f;
    {
        const float* vrow = V + (size_t)(row0 + lr) * D + q * 4;
        #pragma unroll 4
        for (int i = 0; i < NCH; ++i) {
            float4 x = *reinterpret_cast<const float4*>(vrow + i * 16);
            if (i == 0 && q == 0) x.x = 0.f;          // zero time coordinate
            svloc += x.x * x.x + x.y * x.y + x.z * x.z + x.w * x.w;
            __half h0 = __float2half_rn(x.x), h1 = __float2half_rn(x.y);
            __half h2 = __float2half_rn(x.z), h3 = __float2half_rn(x.w);
            __half l0 = __float2half_rn(x.x - __half2float(h0));
            __half l1 = __float2half_rn(x.y - __half2float(h1));
            __half l2 = __float2half_rn(x.z - __half2float(h2));
            __half l3 = __float2half_rn(x.w - __half2float(h3));
            char* dst = smc + i * 4096 + aStsOff;
            *reinterpret_cast<uint2*>(dst) =
                make_uint2(packh(h0, h1), packh(h2, h3));
            *reinterpret_cast<uint2*>(dst + 2048) =
                make_uint2(packh(l0, l1), packh(l2, l3));
        }
    }

    // ldmatrix lane offsets
    uint32_t aoff[2];
    {
        int m = lane >> 3;
        int tsel = ((m & 1) << 1) | (m >> 1);    // matrix -> tile {0,2,1,3}
        #pragma unroll
        for (int mt = 0; mt < 2; ++mt) {
            int rtm = wm * 4 + mt * 2;
            aoff[mt] = (uint32_t)((rtm * 2 + tsel) * 128 + (lane & 7) * 16);
        }
    }
    const uint32_t boff = (uint32_t)((lane >> 3) * 128 + (lane & 7) * 16);

    // group 0 done (group 1 may still fly), A tile visible to all warps
    CP_WAIT1();
    __syncthreads();

    float acc[2][8][4];
    #pragma unroll
    for (int mt = 0; mt < 2; ++mt)
        #pragma unroll
        for (int nt = 0; nt < 8; ++nt)
            #pragma unroll
            for (int e = 0; e < 4; ++e) acc[mt][nt][e] = 0.f;

    // A fragments for chunk 0
    uint32_t ah[2][4], alo[2][4];
    #pragma unroll
    for (int mt = 0; mt < 2; ++mt) {
        LDSM4(ah[mt],  smem0 + aoff[mt]);
        LDSM4(alo[mt], smem0 + 2048 + aoff[mt]);
    }

    // ---- mainloop ----
    for (int i = 0; i < NCH; ++i) {
        // stage (i+2)%3 was last read at chunk i-1 (barrier passed) -> free
        if (i + 2 < NCH) cp_w(i + 2, (i + 2) % 3);

        const uint32_t wb = smem0 + A_BYTES + (i % 3) * WSTAGE_B
                          + wn * 8 * 512 + boff;
        uint32_t bq[2][4];
        LDSM4(bq[0], wb);
        #pragma unroll
        for (int nt = 0; nt < 8; ++nt) {
            int cur = nt & 1;
            if (nt < 7) LDSM4(bq[cur ^ 1], wb + (nt + 1) * 512);
            #pragma unroll
            for (int mt = 0; mt < 2; ++mt) {
                MMAF16(acc[mt][nt], ah[mt],  bq[cur][0], bq[cur][1]);  // hi*hi
                MMAF16(acc[mt][nt], ah[mt],  bq[cur][2], bq[cur][3]);  // hi*lo
                MMAF16(acc[mt][nt], alo[mt], bq[cur][0], bq[cur][1]);  // lo*hi
            }
        }

        // A fragments for chunk i+1 (resident region, no hazard; after last
        // use of the current fragments so the registers just rotate)
        if (i + 1 < NCH) {
            const uint32_t ab = smem0 + (i + 1) * 4096;
            #pragma unroll
            for (int mt = 0; mt < 2; ++mt) {
                LDSM4(ah[mt],  ab + aoff[mt]);
                LDSM4(alo[mt], ab + 2048 + aoff[mt]);
            }
        }

        // steady state: group i+1 committed 2 chunks ago -> wait is a no-op
        if (i < NCH - 2) { CP_WAIT1(); } else { CP_WAIT0(); }
        __syncthreads();
    }

    // ---- Sv + bias into alias region (stage 0; safe after final barrier) ----
    svloc += __shfl_xor_sync(~0u, svloc, 1);
    svloc += __shfl_xor_sync(~0u, svloc, 2);
    if (q == 0) svsum[lr] = svloc;
    {
        float bv = (tid == 0) ? 0.f : __ldg(&bias[tid - 1]);
        sbias[tid] = bv;
        float sq = bv * bv;
        #pragma unroll
        for (int o = 16; o > 0; o >>= 1) sq += __shfl_xor_sync(~0u, sq, o);
        if (lane == 0) sred[wid] = sq;
    }
    __syncthreads();
    if (tid == 0) {
        float s = 0.f;
        #pragma unroll
        for (int i = 0; i < 8; i++) s += sred[i];
        *sSb = s;
    }

    // per-thread partial Sg/dg over its 16 columns x 4 rows
    float psg[4] = {0.f, 0.f, 0.f, 0.f};
    float pdg[4] = {0.f, 0.f, 0.f, 0.f};
    const bool isc0 = (wn == 0 && (lane & 3) == 0);   // col0 owner when nt==0
    #pragma unroll
    for (int nt = 0; nt < 8; ++nt) {
        float2 bf = *reinterpret_cast<const float2*>(
            &sbias[wn * 64 + nt * 8 + 2 * (lane & 3)]);
        #pragma unroll
        for (int mt = 0; mt < 2; ++mt) {
            const float* C = acc[mt][nt];
            if (!(isc0 && nt == 0)) {             // exclude column 0
                psg[mt * 2]     = fmaf(C[0], C[0], psg[mt * 2]);
                pdg[mt * 2]     = fmaf(C[0], bf.x, pdg[mt * 2]);
                psg[mt * 2 + 1] = fmaf(C[2], C[2], psg[mt * 2 + 1]);
                pdg[mt * 2 + 1] = fmaf(C[2], bf.x, pdg[mt * 2 + 1]);
            }
            psg[mt * 2]     = fmaf(C[1], C[1], psg[mt * 2]);
            pdg[mt * 2]     = fmaf(C[1], bf.y, pdg[mt * 2]);
            psg[mt * 2 + 1] = fmaf(C[3], C[3], psg[mt * 2 + 1]);
            pdg[mt * 2 + 1] = fmaf(C[3], bf.y, pdg[mt * 2 + 1]);
        }
    }
    #pragma unroll
    for (int e = 0; e < 4; ++e) {
        psg[e] += __shfl_xor_sync(~0u, psg[e], 1);
        psg[e] += __shfl_xor_sync(~0u, psg[e], 2);
        pdg[e] += __shfl_xor_sync(~0u, pdg[e], 1);
        pdg[e] += __shfl_xor_sync(~0u, pdg[e], 2);
    }
    if ((lane & 3) == 0) {
        int r0 = wm * 32 + (lane >> 2);
        sgp[(r0)      * 4 + wn] = psg[0];  sdgp[(r0)      * 4 + wn] = pdg[0];
        sgp[(r0 + 8)  * 4 + wn] = psg[1];  sdgp[(r0 + 8)  * 4 + wn] = pdg[1];
        sgp[(r0 + 16) * 4 + wn] = psg[2];  sdgp[(r0 + 16) * 4 + wn] = pdg[2];
        sgp[(r0 + 24) * 4 + wn] = psg[3];  sdgp[(r0 + 24) * 4 + wn] = pdg[3];
    }
    __syncthreads();

    if (tid < 64) {
        float Sg = sgp[tid * 4] + sgp[tid * 4 + 1] + sgp[tid * 4 + 2] + sgp[tid * 4 + 3];
        float dg = sdgp[tid * 4] + sdgp[tid * 4 + 1] + sdgp[tid * 4 + 2] + sdgp[tid * 4 + 3];

        const float c   = *cin_p;
        const float c2  = *cout_p;
        const float sqc = sqrtf(c);
        const float sq2 = sqrtf(c2);
        const float Sb  = *sSb;
        const float Sv  = svsum[tid];

        const float v0p  = sqrtf(c + Sv);
        const float m    = (sqc * acoshf(fmaxf(v0p / sqc - EPSF, ACOSH_MINF)))
                           / (sqrtf(Sv) + EPSF);
        const float Sw   = m * m * Sg;
        const float dw   = m * dg;
        const float n    = sqrtf(Sw) / sqc + EPSF;
        const float ncl  = fminf(n, CLIPF);
        const float ch   = coshf(ncl);
        const float sfac = sinhf(ncl) / n;
        const float T    = sfac * sfac * Sw;
        const float hp0  = sqrtf(c + T);
        const float dd   = sqc * acoshf(fmaxf(ch, ACOSH_MINF));
        const float d2   = sqc * acoshf(fmaxf(hp0 / sqc - EPSF, ACOSH_MINF));
        const float u0   = sqc - hp0 * hp0 / sqc;
        const float suj2 = (hp0 * hp0 / c) * T;
        const float nrmu = sqrtf(suj2 - u0 * u0);
        const float mlt  = d2 / (nrmu + EPSF);
        const float alph = 1.f - mlt * (hp0 / sqc) * sfac;
        const float m2   = dw / (dd * dd);
        const float beta = alph * m2;
        const float bt0  = -(mlt * u0) * m2;
        const float btsq = bt0 * bt0 + Sb - 2.f * beta * dw + beta * beta * Sw;
        const float nb   = sqrtf(btsq) / sqc + EPSF;
        const float nbcl = fminf(nb, CLIPF);
        const float chb  = coshf(nbcl);
        const float sfb  = sinhf(nbcl) / nb;
        const float gam  = chb * sfac - sfb * beta;
        const float del  = sfb;
        const float Sbi  = gam * gam * Sw + 2.f * gam * del * dw + del * del * Sb;
        const float p0   = sqrtf(c + Sbi);
        const float d3   = sqc * acoshf(fmaxf(p0 / sqc - EPSF, ACOSH_MINF));
        const float qn   = sqrtf(Sbi);
        const float mlt3 = d3 / (qn + EPSF);
        const float nf   = mlt3 * qn / sq2 + EPSF;
        const float nfcl = fminf(nf, CLIPF);
        const float phi  = (sinhf(nfcl) / nf) * mlt3;
        sAw[tid] = phi * gam * m;
        sAb[tid] = phi * del;
        sO0[tid] = sq2 * coshf(nfcl);
    }
    __syncthreads();

    // stores
    #pragma unroll
    for (int mt = 0; mt < 2; ++mt) {
        #pragma unroll
        for (int rp = 0; rp < 2; ++rp) {
            int r = wm * 32 + mt * 16 + rp * 8 + (lane >> 2);
            float Aw = sAw[r], Ab = sAb[r];
            float* orow = out + (size_t)(row0 + r) * D;
            #pragma unroll
            for (int nt = 0; nt < 8; ++nt) {
                float2 bf = *reinterpret_cast<const float2*>(
                    &sbias[wn * 64 + nt * 8 + 2 * (lane & 3)]);
                float g0 = acc[mt][nt][rp * 2];
                float g1 = acc[mt][nt][rp * 2 + 1];
                float2 o;
                o.x = fmaf(Aw, g0, Ab * bf.x);
                o.y = fmaf(Aw, g1, Ab * bf.y);
                if (wn == 0 && nt == 0 && (lane & 3) == 0) o.x = sO0[r];
                *reinterpret_cast<float2*>(
                    orow + wn * 64 + nt * 8 + 2 * (lane & 3)) = o;
            }
        }
    }
}

extern "C" void kernel_launch(void* const* d_in, const int* in_sizes, int n_in,
                              void* d_out, int out_size)
{
    const float* V    = (const float*)d_in[0];
    const float* cin  = (const float*)d_in[1];
    const float* cout = (const float*)d_in[2];
    const float* W    = (const float*)d_in[3];
    const float* bias = (const float*)d_in[4];
    float* out = (float*)d_out;

    const int nrow = in_sizes[0] / D;             // 131072

    cudaFuncSetAttribute(dh_mma, cudaFuncAttributeMaxDynamicSharedMemorySize,
                         SMEM_DYN);

    prep_w<<<32, 256>>>(W);
    dh_mma<<<nrow / BM, NT, SMEM_DYN>>>(V, cin, cout, bias, out);
}

// round 10
// speedup vs baseline: 1.2782x; 1.2782x over previous
#include <cuda_runtime.h>
#include <cuda_fp16.h>
#include <cstdint>
#include <math.h>

// DenseHyperbolic: fused GEMM (mma.sync m16n8k16 fp16, 2-term Markidis split:
// a_hi*b_hi + a_hi*b_lo, dropping a_lo*b_hi) + analytic hyperbolic epilogue.
//   g = v'(col0=0) @ W ; out_j = Aw*g_j + Ab*bias_j ; out_0 = sqrt(c2)*cosh(.)
//
// R9 micro-scheduling regressed; this is R8's exact (best) structure with the
// third MMA term removed: tensor work 97us -> ~65us, A resident tile halves
// to 32KB (hi only), 2 fewer LDSM4 per warp-chunk. Expected rel_err ~1-3e-4
// (error = a_lo*b ~ 2^-11 relative per product, sqrt(K) accumulation), vs
// the 1e-3 gate. 64KB smem/CTA, 2 CTAs/SM.

constexpr int D   = 256;
constexpr int BM  = 64;
constexpr int NCH = 16;            // chunks of K=16
constexpr int NT  = 256;
constexpr int A_BYTES  = 32768;    // 16 chunks x 2KB (hi only)
constexpr int WSTAGE_B = 16384;
constexpr int SMEM_DYN = A_BYTES + 2 * WSTAGE_B;   // 64 KB

#define EPSF       1e-4f
#define ACOSH_MINF 1.0001f
#define CLIPF      8.0f

// W image: [16 chunks][32 ngroups][4 tiles: hiK0|hiK1|loK0|loK1][64 halves]
__device__ __half w_img[16 * 8192];

__device__ __forceinline__ uint32_t smem_u32(const void* p) {
    uint32_t a;
    asm("{ .reg .u64 t; cvta.to.shared.u64 t, %1; cvt.u32.u64 %0, t; }"
        : "=r"(a) : "l"(p));
    return a;
}
__device__ __forceinline__ uint32_t packh(__half a, __half b) {
    __half2 h = __halves2half2(a, b);
    return *reinterpret_cast<uint32_t*>(&h);
}

#define MMAF16(C, A, b0, b1) \
    asm volatile("mma.sync.aligned.m16n8k16.row.col.f32.f16.f16.f32 " \
        "{%0,%1,%2,%3}, {%4,%5,%6,%7}, {%8,%9}, {%0,%1,%2,%3};" \
        : "+f"((C)[0]), "+f"((C)[1]), "+f"((C)[2]), "+f"((C)[3]) \
        : "r"((A)[0]), "r"((A)[1]), "r"((A)[2]), "r"((A)[3]), \
          "r"(b0), "r"(b1))

#define LDSM4(R, addr) \
    asm volatile("ldmatrix.sync.aligned.m8n8.x4.shared.b16 {%0,%1,%2,%3}, [%4];" \
        : "=r"((R)[0]), "=r"((R)[1]), "=r"((R)[2]), "=r"((R)[3]) : "r"(addr))

#define CP_ASYNC16(dst_u32, src_ptr) \
    asm volatile("cp.async.cg.shared.global [%0], [%1], 16;" \
                 :: "r"(dst_u32), "l"(src_ptr))
#define CP_COMMIT() asm volatile("cp.async.commit_group;")
#define CP_WAIT0()  asm volatile("cp.async.wait_group 0;" ::: "memory")

// ---- prep: W[k][n] row-major -> fragment-tiled fp16 hi/lo image ----
__global__ void prep_w(const float* __restrict__ W) {
    int t = blockIdx.x * 256 + threadIdx.x;      // 8192 tasks
    int c  = t >> 9;                             // k16 chunk
    int rm = t & 511;
    int ng = rm >> 4;                            // n group (8 cols)
    int kt = (rm >> 3) & 1;
    int rr = rm & 7;                             // n within group
    int n  = ng * 8 + rr;
    int kb = c * 16 + kt * 8;
    __half h[8], l[8];
    #pragma unroll
    for (int j = 0; j < 8; ++j) {
        float v  = W[(size_t)(kb + j) * 256 + n];
        __half hi = __float2half_rn(v);
        h[j] = hi;
        l[j] = __float2half_rn(v - __half2float(hi));
    }
    size_t base = (size_t)c * 8192 + ng * 256 + kt * 64 + rr * 8;   // halves
    *reinterpret_cast<uint4*>(w_img + base)       = *reinterpret_cast<const uint4*>(h);
    *reinterpret_cast<uint4*>(w_img + base + 128) = *reinterpret_cast<const uint4*>(l);
}

// ---- main kernel ----
__global__ __launch_bounds__(NT, 2)
void dh_mma(const float* __restrict__ V,
            const float* __restrict__ cin_p,
            const float* __restrict__ cout_p,
            const float* __restrict__ bias,
            float* __restrict__ out)
{
    extern __shared__ __align__(16) char smc[];   // A 32KB | W stages 32KB
    const int tid  = threadIdx.x;
    const int lane = tid & 31;
    const int wid  = tid >> 5;
    const int wm   = wid >> 2;        // 0..1 (M)
    const int wn   = wid & 3;         // 0..3 (N)
    const int row0 = blockIdx.x * BM;
    const uint32_t smem0 = smem_u32(smc);

    // epilogue alias region (inside W stage 0; used only after mainloop)
    float* al     = reinterpret_cast<float*>(smc + A_BYTES);
    float* sbias  = al;               // 256
    float* sgp    = al + 256;         // 64 x 4
    float* sdgp   = al + 512;         // 64 x 4
    float* svsum  = al + 768;         // 64
    float* sAw    = al + 832;
    float* sAb    = al + 896;
    float* sO0    = al + 960;
    float* sred   = al + 1024;        // 8
    float* sSb    = al + 1032;

    // ---- W stage cp.async (16KB linear copy) ----
    auto cp_w = [&](int i, int stg) {
        const __half* src = w_img + (size_t)i * 8192;
        uint32_t dst = smem0 + A_BYTES + stg * WSTAGE_B;
        #pragma unroll
        for (int j = 0; j < 4; ++j) {
            int f = tid + j * 256;               // 16B units, 0..1023
            CP_ASYNC16(dst + f * 16, src + f * 8);
        }
        CP_COMMIT();
    };

    // first W copy flies during the whole A prologue
    cp_w(0, 0);

    // ---- A prologue: convert 64x256 tile to hi fp16, resident in smem ----
    // thread: row lr = tid>>2, float4 slot q = tid&3 per chunk
    const int lr = tid >> 2;
    const int q  = tid & 3;
    const uint32_t aStsOff = (uint32_t)(((lr >> 3) * 2 + (q >> 1)) * 128
                                        + (lr & 7) * 16 + (q & 1) * 8);
    float svloc = 0.f;
    {
        const float* vrow = V + (size_t)(row0 + lr) * D + q * 4;
        #pragma unroll 4
        for (int i = 0; i < NCH; ++i) {
            float4 x = *reinterpret_cast<const float4*>(vrow + i * 16);
            if (i == 0 && q == 0) x.x = 0.f;          // zero time coordinate
            svloc += x.x * x.x + x.y * x.y + x.z * x.z + x.w * x.w;
            __half h0 = __float2half_rn(x.x), h1 = __float2half_rn(x.y);
            __half h2 = __float2half_rn(x.z), h3 = __float2half_rn(x.w);
            char* dst = smc + i * 2048 + aStsOff;
            *reinterpret_cast<uint2*>(dst) =
                make_uint2(packh(h0, h1), packh(h2, h3));
        }
    }

    // ldmatrix lane offsets
    uint32_t aoff[2];
    {
        int m = lane >> 3;
        int tsel = ((m & 1) << 1) | (m >> 1);    // matrix -> tile {0,2,1,3}
        #pragma unroll
        for (int mt = 0; mt < 2; ++mt) {
            int rtm = wm * 4 + mt * 2;
            aoff[mt] = (uint32_t)((rtm * 2 + tsel) * 128 + (lane & 7) * 16);
        }
    }
    const uint32_t boff = (uint32_t)((lane >> 3) * 128 + (lane & 7) * 16);

    float acc[2][8][4];
    #pragma unroll
    for (int mt = 0; mt < 2; ++mt)
        #pragma unroll
        for (int nt = 0; nt < 8; ++nt)
            #pragma unroll
            for (int e = 0; e < 4; ++e) acc[mt][nt][e] = 0.f;

    // ---- mainloop: pure ldmatrix + MMA; one barrier per chunk ----
    for (int i = 0; i < NCH; ++i) {
        CP_WAIT0();                    // group i complete (lead-1)
        __syncthreads();               // visibility; stage (i+1)&1 is free
        if (i + 1 < NCH) cp_w(i + 1, (i + 1) & 1);

        const uint32_t ab = smem0 + i * 2048;
        uint32_t ah[2][4];
        #pragma unroll
        for (int mt = 0; mt < 2; ++mt) LDSM4(ah[mt], ab + aoff[mt]);

        const uint32_t wb = smem0 + A_BYTES + (i & 1) * WSTAGE_B
                          + wn * 8 * 512 + boff;
        #pragma unroll
        for (int nt = 0; nt < 8; ++nt) {
            uint32_t bq[4];
            LDSM4(bq, wb + nt * 512);
            #pragma unroll
            for (int mt = 0; mt < 2; ++mt) {
                MMAF16(acc[mt][nt], ah[mt], bq[0], bq[1]);   // hi*hi
                MMAF16(acc[mt][nt], ah[mt], bq[2], bq[3]);   // hi*lo
            }
        }
    }
    __syncthreads();                   // all MMA done; alias region reusable

    // ---- Sv + bias into alias region ----
    svloc += __shfl_xor_sync(~0u, svloc, 1);
    svloc += __shfl_xor_sync(~0u, svloc, 2);
    if (q == 0) svsum[lr] = svloc;
    {
        float bv = (tid == 0) ? 0.f : __ldg(&bias[tid - 1]);
        sbias[tid] = bv;
        float sq = bv * bv;
        #pragma unroll
        for (int o = 16; o > 0; o >>= 1) sq += __shfl_xor_sync(~0u, sq, o);
        if (lane == 0) sred[wid] = sq;
    }
    __syncthreads();
    if (tid == 0) {
        float s = 0.f;
        #pragma unroll
        for (int i = 0; i < 8; i++) s += sred[i];
        *sSb = s;
    }

    // per-thread partial Sg/dg over its 16 columns x 4 rows
    float psg[4] = {0.f, 0.f, 0.f, 0.f};
    float pdg[4] = {0.f, 0.f, 0.f, 0.f};
    const bool isc0 = (wn == 0 && (lane & 3) == 0);   // col0 owner when nt==0
    #pragma unroll
    for (int nt = 0; nt < 8; ++nt) {
        float2 bf = *reinterpret_cast<const float2*>(
            &sbias[wn * 64 + nt * 8 + 2 * (lane & 3)]);
        #pragma unroll
        for (int mt = 0; mt < 2; ++mt) {
            const float* C = acc[mt][nt];
            if (!(isc0 && nt == 0)) {             // exclude column 0
                psg[mt * 2]     = fmaf(C[0], C[0], psg[mt * 2]);
                pdg[mt * 2]     = fmaf(C[0], bf.x, pdg[mt * 2]);
                psg[mt * 2 + 1] = fmaf(C[2], C[2], psg[mt * 2 + 1]);
                pdg[mt * 2 + 1] = fmaf(C[2], bf.x, pdg[mt * 2 + 1]);
            }
            psg[mt * 2]     = fmaf(C[1], C[1], psg[mt * 2]);
            pdg[mt * 2]     = fmaf(C[1], bf.y, pdg[mt * 2]);
            psg[mt * 2 + 1] = fmaf(C[3], C[3], psg[mt * 2 + 1]);
            pdg[mt * 2 + 1] = fmaf(C[3], bf.y, pdg[mt * 2 + 1]);
        }
    }
    #pragma unroll
    for (int e = 0; e < 4; ++e) {
        psg[e] += __shfl_xor_sync(~0u, psg[e], 1);
        psg[e] += __shfl_xor_sync(~0u, psg[e], 2);
        pdg[e] += __shfl_xor_sync(~0u, pdg[e], 1);
        pdg[e] += __shfl_xor_sync(~0u, pdg[e], 2);
    }
    if ((lane & 3) == 0) {
        int r0 = wm * 32 + (lane >> 2);
        sgp[(r0)      * 4 + wn] = psg[0];  sdgp[(r0)      * 4 + wn] = pdg[0];
        sgp[(r0 + 8)  * 4 + wn] = psg[1];  sdgp[(r0 + 8)  * 4 + wn] = pdg[1];
        sgp[(r0 + 16) * 4 + wn] = psg[2];  sdgp[(r0 + 16) * 4 + wn] = pdg[2];
        sgp[(r0 + 24) * 4 + wn] = psg[3];  sdgp[(r0 + 24) * 4 + wn] = pdg[3];
    }
    __syncthreads();

    if (tid < 64) {
        float Sg = sgp[tid * 4] + sgp[tid * 4 + 1] + sgp[tid * 4 + 2] + sgp[tid * 4 + 3];
        float dg = sdgp[tid * 4] + sdgp[tid * 4 + 1] + sdgp[tid * 4 + 2] + sdgp[tid * 4 + 3];

        const float c   = *cin_p;
        const float c2  = *cout_p;
        const float sqc = sqrtf(c);
        const float sq2 = sqrtf(c2);
        const float Sb  = *sSb;
        const float Sv  = svsum[tid];

        const float v0p  = sqrtf(c + Sv);
        const float m    = (sqc * acoshf(fmaxf(v0p / sqc - EPSF, ACOSH_MINF)))
                           / (sqrtf(Sv) + EPSF);
        const float Sw   = m * m * Sg;
        const float dw   = m * dg;
        const float n    = sqrtf(Sw) / sqc + EPSF;
        const float ncl  = fminf(n, CLIPF);
        const float ch   = coshf(ncl);
        const float sfac = sinhf(ncl) / n;
        const float T    = sfac * sfac * Sw;
        const float hp0  = sqrtf(c + T);
        const float dd   = sqc * acoshf(fmaxf(ch, ACOSH_MINF));
        const float d2   = sqc * acoshf(fmaxf(hp0 / sqc - EPSF, ACOSH_MINF));
        const float u0   = sqc - hp0 * hp0 / sqc;
        const float suj2 = (hp0 * hp0 / c) * T;
        const float nrmu = sqrtf(suj2 - u0 * u0);
        const float mlt  = d2 / (nrmu + EPSF);
        const float alph = 1.f - mlt * (hp0 / sqc) * sfac;
        const float m2   = dw / (dd * dd);
        const float beta = alph * m2;
        const float bt0  = -(mlt * u0) * m2;
        const float btsq = bt0 * bt0 + Sb - 2.f * beta * dw + beta * beta * Sw;
        const float nb   = sqrtf(btsq) / sqc + EPSF;
        const float nbcl = fminf(nb, CLIPF);
        const float chb  = coshf(nbcl);
        const float sfb  = sinhf(nbcl) / nb;
        const float gam  = chb * sfac - sfb * beta;
        const float del  = sfb;
        const float Sbi  = gam * gam * Sw + 2.f * gam * del * dw + del * del * Sb;
        const float p0   = sqrtf(c + Sbi);
        const float d3   = sqc * acoshf(fmaxf(p0 / sqc - EPSF, ACOSH_MINF));
        const float qn   = sqrtf(Sbi);
        const float mlt3 = d3 / (qn + EPSF);
        const float nf   = mlt3 * qn / sq2 + EPSF;
        const float nfcl = fminf(nf, CLIPF);
        const float phi  = (sinhf(nfcl) / nf) * mlt3;
        sAw[tid] = phi * gam * m;
        sAb[tid] = phi * del;
        sO0[tid] = sq2 * coshf(nfcl);
    }
    __syncthreads();

    // stores
    #pragma unroll
    for (int mt = 0; mt < 2; ++mt) {
        #pragma unroll
        for (int rp = 0; rp < 2; ++rp) {
            int r = wm * 32 + mt * 16 + rp * 8 + (lane >> 2);
            float Aw = sAw[r], Ab = sAb[r];
            float* orow = out + (size_t)(row0 + r) * D;
            #pragma unroll
            for (int nt = 0; nt < 8; ++nt) {
                float2 bf = *reinterpret_cast<const float2*>(
                    &sbias[wn * 64 + nt * 8 + 2 * (lane & 3)]);
                float g0 = acc[mt][nt][rp * 2];
                float g1 = acc[mt][nt][rp * 2 + 1];
                float2 o;
                o.x = fmaf(Aw, g0, Ab * bf.x);
                o.y = fmaf(Aw, g1, Ab * bf.y);
                if (wn == 0 && nt == 0 && (lane & 3) == 0) o.x = sO0[r];
                *reinterpret_cast<float2*>(
                    orow + wn * 64 + nt * 8 + 2 * (lane & 3)) = o;
            }
        }
    }
}

extern "C" void kernel_launch(void* const* d_in, const int* in_sizes, int n_in,
                              void* d_out, int out_size)
{
    const float* V    = (const float*)d_in[0];
    const float* cin  = (const float*)d_in[1];
    const float* cout = (const float*)d_in[2];
    const float* W    = (const float*)d_in[3];
    const float* bias = (const float*)d_in[4];
    float* out = (float*)d_out;

    const int nrow = in_sizes[0] / D;             // 131072

    cudaFuncSetAttribute(dh_mma, cudaFuncAttributeMaxDynamicSharedMemorySize,
                         SMEM_DYN);

    prep_w<<<32, 256>>>(W);
    dh_mma<<<nrow / BM, NT, SMEM_DYN>>>(V, cin, cout, bias, out);
}

// round 11
// speedup vs baseline: 1.4237x; 1.1138x over previous
#include <cuda_runtime.h>
#include <cuda_fp16.h>
#include <cstdint>
#include <math.h>

// DenseHyperbolic: fused GEMM (mma.sync m16n8k16 fp16, 2-term Markidis split:
// a_hi*b_hi + a_hi*b_lo) + analytic hyperbolic epilogue.
//   g = v'(col0=0) @ W ; out_j = Aw*g_j + Ab*bias_j ; out_0 = sqrt(c2)*cosh(.)
//
// R10 diagnosis: ~84us exposed on the per-chunk CP_WAIT+__syncthreads convoy
// (overhead GREW as MMA work shrank). R11: warp-private W pipelines. Each
// warp cp.asyncs only its own wn-slice (4KB, contiguous in the fragment
// image) into a private double buffer; cp.async wait_group is per-thread, so
// wait_group + __syncwarp replaces ALL CTA barriers in the mainloop. A is
// smem-resident (one prologue sync). 96KB/CTA, 2 CTAs/SM.

constexpr int D   = 256;
constexpr int BM  = 64;
constexpr int NCH = 16;            // chunks of K=16
constexpr int NT  = 256;
constexpr int A_BYTES = 32768;     // 16 chunks x 2KB (hi only)
constexpr int WSTG_B  = 4096;      // per warp per stage (wn slice)
constexpr int SMEM_DYN = A_BYTES + 8 * 2 * WSTG_B;   // 96 KB

#define EPSF       1e-4f
#define ACOSH_MINF 1.0001f
#define CLIPF      8.0f

// W image: [16 chunks][32 ngroups][4 tiles: hiK0|hiK1|loK0|loK1][64 halves]
__device__ __half w_img[16 * 8192];

__device__ __forceinline__ uint32_t smem_u32(const void* p) {
    uint32_t a;
    asm("{ .reg .u64 t; cvta.to.shared.u64 t, %1; cvt.u32.u64 %0, t; }"
        : "=r"(a) : "l"(p));
    return a;
}
__device__ __forceinline__ uint32_t packh(__half a, __half b) {
    __half2 h = __halves2half2(a, b);
    return *reinterpret_cast<uint32_t*>(&h);
}

#define MMAF16(C, A, b0, b1) \
    asm volatile("mma.sync.aligned.m16n8k16.row.col.f32.f16.f16.f32 " \
        "{%0,%1,%2,%3}, {%4,%5,%6,%7}, {%8,%9}, {%0,%1,%2,%3};" \
        : "+f"((C)[0]), "+f"((C)[1]), "+f"((C)[2]), "+f"((C)[3]) \
        : "r"((A)[0]), "r"((A)[1]), "r"((A)[2]), "r"((A)[3]), \
          "r"(b0), "r"(b1))

#define LDSM4(R, addr) \
    asm volatile("ldmatrix.sync.aligned.m8n8.x4.shared.b16 {%0,%1,%2,%3}, [%4];" \
        : "=r"((R)[0]), "=r"((R)[1]), "=r"((R)[2]), "=r"((R)[3]) : "r"(addr))

#define CP_ASYNC16(dst_u32, src_ptr) \
    asm volatile("cp.async.cg.shared.global [%0], [%1], 16;" \
                 :: "r"(dst_u32), "l"(src_ptr))
#define CP_COMMIT() asm volatile("cp.async.commit_group;")
#define CP_WAIT0()  asm volatile("cp.async.wait_group 0;" ::: "memory")
#define CP_WAIT1()  asm volatile("cp.async.wait_group 1;" ::: "memory")

// ---- prep: W[k][n] row-major -> fragment-tiled fp16 hi/lo image ----
__global__ void prep_w(const float* __restrict__ W) {
    int t = blockIdx.x * 256 + threadIdx.x;      // 8192 tasks
    int c  = t >> 9;                             // k16 chunk
    int rm = t & 511;
    int ng = rm >> 4;                            // n group (8 cols)
    int kt = (rm >> 3) & 1;
    int rr = rm & 7;                             // n within group
    int n  = ng * 8 + rr;
    int kb = c * 16 + kt * 8;
    __half h[8], l[8];
    #pragma unroll
    for (int j = 0; j < 8; ++j) {
        float v  = W[(size_t)(kb + j) * 256 + n];
        __half hi = __float2half_rn(v);
        h[j] = hi;
        l[j] = __float2half_rn(v - __half2float(hi));
    }
    size_t base = (size_t)c * 8192 + ng * 256 + kt * 64 + rr * 8;   // halves
    *reinterpret_cast<uint4*>(w_img + base)       = *reinterpret_cast<const uint4*>(h);
    *reinterpret_cast<uint4*>(w_img + base + 128) = *reinterpret_cast<const uint4*>(l);
}

// ---- main kernel ----
__global__ __launch_bounds__(NT, 2)
void dh_mma(const float* __restrict__ V,
            const float* __restrict__ cin_p,
            const float* __restrict__ cout_p,
            const float* __restrict__ bias,
            float* __restrict__ out)
{
    extern __shared__ __align__(16) char smc[];   // A 32KB | warp stages 64KB
    const int tid  = threadIdx.x;
    const int lane = tid & 31;
    const int wid  = tid >> 5;
    const int wm   = wid >> 2;        // 0..1 (M)
    const int wn   = wid & 3;         // 0..3 (N)
    const int row0 = blockIdx.x * BM;
    const uint32_t smem0 = smem_u32(smc);

    // epilogue alias region (inside warp-stage area; used only after mainloop)
    float* al     = reinterpret_cast<float*>(smc + A_BYTES);
    float* sbias  = al;               // 256
    float* sgp    = al + 256;         // 64 x 4
    float* sdgp   = al + 512;         // 64 x 4
    float* svsum  = al + 768;         // 64
    float* sAw    = al + 832;
    float* sAb    = al + 896;
    float* sO0    = al + 960;
    float* sred   = al + 1024;        // 8
    float* sSb    = al + 1032;

    // ---- warp-private W slice cp.async (4KB contiguous) ----
    auto cp_w = [&](int i, int stg) {
        const __half* src = w_img + (size_t)i * 8192 + wn * 2048;
        uint32_t dst = smem0 + A_BYTES + (uint32_t)(wid * 2 + stg) * WSTG_B;
        #pragma unroll
        for (int j = 0; j < 8; ++j) {
            int f = lane + j * 32;               // 16B units, 0..255
            CP_ASYNC16(dst + f * 16, src + f * 8);
        }
        CP_COMMIT();
    };

    // lead-2 prologue flies during the A conversion
    cp_w(0, 0);
    cp_w(1, 1);

    // ---- A prologue: convert 64x256 tile to hi fp16, resident in smem ----
    const int lr = tid >> 2;
    const int q  = tid & 3;
    const uint32_t aStsOff = (uint32_t)(((lr >> 3) * 2 + (q >> 1)) * 128
                                        + (lr & 7) * 16 + (q & 1) * 8);
    float svloc = 0.f;
    {
        const float* vrow = V + (size_t)(row0 + lr) * D + q * 4;
        #pragma unroll 4
        for (int i = 0; i < NCH; ++i) {
            float4 x = *reinterpret_cast<const float4*>(vrow + i * 16);
            if (i == 0 && q == 0) x.x = 0.f;          // zero time coordinate
            svloc += x.x * x.x + x.y * x.y + x.z * x.z + x.w * x.w;
            __half h0 = __float2half_rn(x.x), h1 = __float2half_rn(x.y);
            __half h2 = __float2half_rn(x.z), h3 = __float2half_rn(x.w);
            char* dst = smc + i * 2048 + aStsOff;
            *reinterpret_cast<uint2*>(dst) =
                make_uint2(packh(h0, h1), packh(h2, h3));
        }
    }

    // ldmatrix lane offsets
    uint32_t aoff[2];
    {
        int m = lane >> 3;
        int tsel = ((m & 1) << 1) | (m >> 1);    // matrix -> tile {0,2,1,3}
        #pragma unroll
        for (int mt = 0; mt < 2; ++mt) {
            int rtm = wm * 4 + mt * 2;
            aoff[mt] = (uint32_t)((rtm * 2 + tsel) * 128 + (lane & 7) * 16);
        }
    }
    const uint32_t boff = (uint32_t)((lane >> 3) * 128 + (lane & 7) * 16);

    // A tile visible to all warps (the ONLY CTA barrier before the epilogue)
    __syncthreads();

    float acc[2][8][4];
    #pragma unroll
    for (int mt = 0; mt < 2; ++mt)
        #pragma unroll
        for (int nt = 0; nt < 8; ++nt)
            #pragma unroll
            for (int e = 0; e < 4; ++e) acc[mt][nt][e] = 0.f;

    // ---- mainloop: warp-private pipeline, NO CTA barriers ----
    for (int i = 0; i < NCH; ++i) {
        if (i < NCH - 1) { CP_WAIT1(); } else { CP_WAIT0(); }   // chunk i done
        __syncwarp();                          // cross-lane visibility

        const uint32_t ab = smem0 + i * 2048;
        uint32_t ah[2][4];
        #pragma unroll
        for (int mt = 0; mt < 2; ++mt) LDSM4(ah[mt], ab + aoff[mt]);

        const uint32_t wb = smem0 + A_BYTES
                          + (uint32_t)(wid * 2 + (i & 1)) * WSTG_B + boff;
        #pragma unroll
        for (int nt = 0; nt < 8; ++nt) {
            uint32_t bq[4];
            LDSM4(bq, wb + nt * 512);
            #pragma unroll
            for (int mt = 0; mt < 2; ++mt) {
                MMAF16(acc[mt][nt], ah[mt], bq[0], bq[1]);   // hi*hi
                MMAF16(acc[mt][nt], ah[mt], bq[2], bq[3]);   // hi*lo
            }
        }

        // refill the stage just consumed (lead-2)
        if (i + 2 < NCH) cp_w(i + 2, i & 1);
    }
    __syncthreads();                   // all warps done; alias region reusable

    // ---- Sv + bias into alias region ----
    svloc += __shfl_xor_sync(~0u, svloc, 1);
    svloc += __shfl_xor_sync(~0u, svloc, 2);
    if (q == 0) svsum[lr] = svloc;
    {
        float bv = (tid == 0) ? 0.f : __ldg(&bias[tid - 1]);
        sbias[tid] = bv;
        float sq = bv * bv;
        #pragma unroll
        for (int o = 16; o > 0; o >>= 1) sq += __shfl_xor_sync(~0u, sq, o);
        if (lane == 0) sred[wid] = sq;
    }
    __syncthreads();
    if (tid == 0) {
        float s = 0.f;
        #pragma unroll
        for (int i = 0; i < 8; i++) s += sred[i];
        *sSb = s;
    }

    // per-thread partial Sg/dg over its 16 columns x 4 rows
    float psg[4] = {0.f, 0.f, 0.f, 0.f};
    float pdg[4] = {0.f, 0.f, 0.f, 0.f};
    const bool isc0 = (wn == 0 && (lane & 3) == 0);   // col0 owner when nt==0
    #pragma unroll
    for (int nt = 0; nt < 8; ++nt) {
        float2 bf = *reinterpret_cast<const float2*>(
            &sbias[wn * 64 + nt * 8 + 2 * (lane & 3)]);
        #pragma unroll
        for (int mt = 0; mt < 2; ++mt) {
            const float* C = acc[mt][nt];
            if (!(isc0 && nt == 0)) {             // exclude column 0
                psg[mt * 2]     = fmaf(C[0], C[0], psg[mt * 2]);
                pdg[mt * 2]     = fmaf(C[0], bf.x, pdg[mt * 2]);
                psg[mt * 2 + 1] = fmaf(C[2], C[2], psg[mt * 2 + 1]);
                pdg[mt * 2 + 1] = fmaf(C[2], bf.x, pdg[mt * 2 + 1]);
            }
            psg[mt * 2]     = fmaf(C[1], C[1], psg[mt * 2]);
            pdg[mt * 2]     = fmaf(C[1], bf.y, pdg[mt * 2]);
            psg[mt * 2 + 1] = fmaf(C[3], C[3], psg[mt * 2 + 1]);
            pdg[mt * 2 + 1] = fmaf(C[3], bf.y, pdg[mt * 2 + 1]);
        }
    }
    #pragma unroll
    for (int e = 0; e < 4; ++e) {
        psg[e] += __shfl_xor_sync(~0u, psg[e], 1);
        psg[e] += __shfl_xor_sync(~0u, psg[e], 2);
        pdg[e] += __shfl_xor_sync(~0u, pdg[e], 1);
        pdg[e] += __shfl_xor_sync(~0u, pdg[e], 2);
    }
    if ((lane & 3) == 0) {
        int r0 = wm * 32 + (lane >> 2);
        sgp[(r0)      * 4 + wn] = psg[0];  sdgp[(r0)      * 4 + wn] = pdg[0];
        sgp[(r0 + 8)  * 4 + wn] = psg[1];  sdgp[(r0 + 8)  * 4 + wn] = pdg[1];
        sgp[(r0 + 16) * 4 + wn] = psg[2];  sdgp[(r0 + 16) * 4 + wn] = pdg[2];
        sgp[(r0 + 24) * 4 + wn] = psg[3];  sdgp[(r0 + 24) * 4 + wn] = pdg[3];
    }
    __syncthreads();

    if (tid < 64) {
        float Sg = sgp[tid * 4] + sgp[tid * 4 + 1] + sgp[tid * 4 + 2] + sgp[tid * 4 + 3];
        float dg = sdgp[tid * 4] + sdgp[tid * 4 + 1] + sdgp[tid * 4 + 2] + sdgp[tid * 4 + 3];

        const float c   = *cin_p;
        const float c2  = *cout_p;
        const float sqc = sqrtf(c);
        const float sq2 = sqrtf(c2);
        const float Sb  = *sSb;
        const float Sv  = svsum[tid];

        const float v0p  = sqrtf(c + Sv);
        const float m    = (sqc * acoshf(fmaxf(v0p / sqc - EPSF, ACOSH_MINF)))
                           / (sqrtf(Sv) + EPSF);
        const float Sw   = m * m * Sg;
        const float dw   = m * dg;
        const float n    = sqrtf(Sw) / sqc + EPSF;
        const float ncl  = fminf(n, CLIPF);
        const float ch   = coshf(ncl);
        const float sfac = sinhf(ncl) / n;
        const float T    = sfac * sfac * Sw;
        const float hp0  = sqrtf(c + T);
        const float dd   = sqc * acoshf(fmaxf(ch, ACOSH_MINF));
        const float d2   = sqc * acoshf(fmaxf(hp0 / sqc - EPSF, ACOSH_MINF));
        const float u0   = sqc - hp0 * hp0 / sqc;
        const float suj2 = (hp0 * hp0 / c) * T;
        const float nrmu = sqrtf(suj2 - u0 * u0);
        const float mlt  = d2 / (nrmu + EPSF);
        const float alph = 1.f - mlt * (hp0 / sqc) * sfac;
        const float m2   = dw / (dd * dd);
        const float beta = alph * m2;
        const float bt0  = -(mlt * u0) * m2;
        const float btsq = bt0 * bt0 + Sb - 2.f * beta * dw + beta * beta * Sw;
        const float nb   = sqrtf(btsq) / sqc + EPSF;
        const float nbcl = fminf(nb, CLIPF);
        const float chb  = coshf(nbcl);
        const float sfb  = sinhf(nbcl) / nb;
        const float gam  = chb * sfac - sfb * beta;
        const float del  = sfb;
        const float Sbi  = gam * gam * Sw + 2.f * gam * del * dw + del * del * Sb;
        const float p0   = sqrtf(c + Sbi);
        const float d3   = sqc * acoshf(fmaxf(p0 / sqc - EPSF, ACOSH_MINF));
        const float qn   = sqrtf(Sbi);
        const float mlt3 = d3 / (qn + EPSF);
        const float nf   = mlt3 * qn / sq2 + EPSF;
        const float nfcl = fminf(nf, CLIPF);
        const float phi  = (sinhf(nfcl) / nf) * mlt3;
        sAw[tid] = phi * gam * m;
        sAb[tid] = phi * del;
        sO0[tid] = sq2 * coshf(nfcl);
    }
    __syncthreads();

    // stores
    #pragma unroll
    for (int mt = 0; mt < 2; ++mt) {
        #pragma unroll
        for (int rp = 0; rp < 2; ++rp) {
            int r = wm * 32 + mt * 16 + rp * 8 + (lane >> 2);
            float Aw = sAw[r], Ab = sAb[r];
            float* orow = out + (size_t)(row0 + r) * D;
            #pragma unroll
            for (int nt = 0; nt < 8; ++nt) {
                float2 bf = *reinterpret_cast<const float2*>(
                    &sbias[wn * 64 + nt * 8 + 2 * (lane & 3)]);
                float g0 = acc[mt][nt][rp * 2];
                float g1 = acc[mt][nt][rp * 2 + 1];
                float2 o;
                o.x = fmaf(Aw, g0, Ab * bf.x);
                o.y = fmaf(Aw, g1, Ab * bf.y);
                if (wn == 0 && nt == 0 && (lane & 3) == 0) o.x = sO0[r];
                *reinterpret_cast<float2*>(
                    orow + wn * 64 + nt * 8 + 2 * (lane & 3)) = o;
            }
        }
    }
}

extern "C" void kernel_launch(void* const* d_in, const int* in_sizes, int n_in,
                              void* d_out, int out_size)
{
    const float* V    = (const float*)d_in[0];
    const float* cin  = (const float*)d_in[1];
    const float* cout = (const float*)d_in[2];
    const float* W    = (const float*)d_in[3];
    const float* bias = (const float*)d_in[4];
    float* out = (float*)d_out;

    const int nrow = in_sizes[0] / D;             // 131072

    cudaFuncSetAttribute(dh_mma, cudaFuncAttributeMaxDynamicSharedMemorySize,
                         SMEM_DYN);

    prep_w<<<32, 256>>>(W);
    dh_mma<<<nrow / BM, NT, SMEM_DYN>>>(V, cin, cout, bias, out);
}

// round 12
// speedup vs baseline: 1.5636x; 1.0983x over previous
#include <cuda_runtime.h>
#include <cuda_fp16.h>
#include <cstdint>
#include <math.h>

// DenseHyperbolic: fused GEMM (mma.sync m16n8k16 fp16, 2-term Markidis split:
// a_hi*b_hi + a_hi*b_lo) + analytic hyperbolic epilogue.
//   g = v'(col0=0) @ W ; out_j = Aw*g_j + Ab*bias_j ; out_0 = sqrt(c2)*cosh(.)
//
// R11: L1 61.6% binding (72 smem wavefronts per warp-chunk vs ~32 tensor
// cycles). R12: warp grid 2Mx4N -> 1Mx8N (warp tile 64x32, mt=4, nt=4).
// B slices disjoint across warps: STS halves, W L2 traffic halves, B LDSM
// halves; net 48 wavefronts per warp-chunk (-33%). Same warp-private
// cp.async pipeline (no CTA barriers in loop), same numerics. 64KB/CTA.

constexpr int D   = 256;
constexpr int BM  = 64;
constexpr int NCH = 16;            // chunks of K=16
constexpr int NT  = 256;
constexpr int A_BYTES = 32768;     // 16 chunks x 2KB (hi only)
constexpr int WSTG_B  = 2048;      // per warp per stage (32-col slice)
constexpr int SMEM_DYN = A_BYTES + 8 * 2 * WSTG_B;   // 64 KB

#define EPSF       1e-4f
#define ACOSH_MINF 1.0001f
#define CLIPF      8.0f

// W image: [16 chunks][32 ngroups][4 tiles: hiK0|hiK1|loK0|loK1][64 halves]
__device__ __half w_img[16 * 8192];

__device__ __forceinline__ uint32_t smem_u32(const void* p) {
    uint32_t a;
    asm("{ .reg .u64 t; cvta.to.shared.u64 t, %1; cvt.u32.u64 %0, t; }"
        : "=r"(a) : "l"(p));
    return a;
}
__device__ __forceinline__ uint32_t packh(__half a, __half b) {
    __half2 h = __halves2half2(a, b);
    return *reinterpret_cast<uint32_t*>(&h);
}

#define MMAF16(C, A, b0, b1) \
    asm volatile("mma.sync.aligned.m16n8k16.row.col.f32.f16.f16.f32 " \
        "{%0,%1,%2,%3}, {%4,%5,%6,%7}, {%8,%9}, {%0,%1,%2,%3};" \
        : "+f"((C)[0]), "+f"((C)[1]), "+f"((C)[2]), "+f"((C)[3]) \
        : "r"((A)[0]), "r"((A)[1]), "r"((A)[2]), "r"((A)[3]), \
          "r"(b0), "r"(b1))

#define LDSM4(R, addr) \
    asm volatile("ldmatrix.sync.aligned.m8n8.x4.shared.b16 {%0,%1,%2,%3}, [%4];" \
        : "=r"((R)[0]), "=r"((R)[1]), "=r"((R)[2]), "=r"((R)[3]) : "r"(addr))

#define CP_ASYNC16(dst_u32, src_ptr) \
    asm volatile("cp.async.cg.shared.global [%0], [%1], 16;" \
                 :: "r"(dst_u32), "l"(src_ptr))
#define CP_COMMIT() asm volatile("cp.async.commit_group;")
#define CP_WAIT0()  asm volatile("cp.async.wait_group 0;" ::: "memory")
#define CP_WAIT1()  asm volatile("cp.async.wait_group 1;" ::: "memory")

// ---- prep: W[k][n] row-major -> fragment-tiled fp16 hi/lo image ----
__global__ void prep_w(const float* __restrict__ W) {
    int t = blockIdx.x * 256 + threadIdx.x;      // 8192 tasks
    int c  = t >> 9;                             // k16 chunk
    int rm = t & 511;
    int ng = rm >> 4;                            // n group (8 cols)
    int kt = (rm >> 3) & 1;
    int rr = rm & 7;                             // n within group
    int n  = ng * 8 + rr;
    int kb = c * 16 + kt * 8;
    __half h[8], l[8];
    #pragma unroll
    for (int j = 0; j < 8; ++j) {
        float v  = W[(size_t)(kb + j) * 256 + n];
        __half hi = __float2half_rn(v);
        h[j] = hi;
        l[j] = __float2half_rn(v - __half2float(hi));
    }
    size_t base = (size_t)c * 8192 + ng * 256 + kt * 64 + rr * 8;   // halves
    *reinterpret_cast<uint4*>(w_img + base)       = *reinterpret_cast<const uint4*>(h);
    *reinterpret_cast<uint4*>(w_img + base + 128) = *reinterpret_cast<const uint4*>(l);
}

// ---- main kernel ----
__global__ __launch_bounds__(NT, 2)
void dh_mma(const float* __restrict__ V,
            const float* __restrict__ cin_p,
            const float* __restrict__ cout_p,
            const float* __restrict__ bias,
            float* __restrict__ out)
{
    extern __shared__ __align__(16) char smc[];   // A 32KB | warp stages 32KB
    const int tid  = threadIdx.x;
    const int lane = tid & 31;
    const int wid  = tid >> 5;
    const int wn   = wid;             // 0..7 (N); warp tile = 64 rows x 32 cols
    const int row0 = blockIdx.x * BM;
    const uint32_t smem0 = smem_u32(smc);

    // epilogue alias region (inside warp-stage area; used only after mainloop)
    float* al     = reinterpret_cast<float*>(smc + A_BYTES);
    float* sbias  = al;               // 256
    float* sgp    = al + 256;         // 64 x 8
    float* sdgp   = al + 768;         // 64 x 8
    float* svsum  = al + 1280;        // 64
    float* sAw    = al + 1344;
    float* sAb    = al + 1408;
    float* sO0    = al + 1472;
    float* sred   = al + 1536;        // 8
    float* sSb    = al + 1544;

    // ---- warp-private W slice cp.async (2KB contiguous: ngroups wn*4..+3) --
    auto cp_w = [&](int i, int stg) {
        const __half* src = w_img + (size_t)i * 8192 + wn * 1024;
        uint32_t dst = smem0 + A_BYTES + (uint32_t)(wid * 2 + stg) * WSTG_B;
        #pragma unroll
        for (int j = 0; j < 4; ++j) {
            int f = lane + j * 32;               // 16B units, 0..127
            CP_ASYNC16(dst + f * 16, src + f * 8);
        }
        CP_COMMIT();
    };

    // lead-2 prologue flies during the A conversion
    cp_w(0, 0);
    cp_w(1, 1);

    // ---- A prologue: convert 64x256 tile to hi fp16, resident in smem ----
    const int lr = tid >> 2;
    const int q  = tid & 3;
    const uint32_t aStsOff = (uint32_t)(((lr >> 3) * 2 + (q >> 1)) * 128
                                        + (lr & 7) * 16 + (q & 1) * 8);
    float svloc = 0.f;
    {
        const float* vrow = V + (size_t)(row0 + lr) * D + q * 4;
        #pragma unroll 4
        for (int i = 0; i < NCH; ++i) {
            float4 x = *reinterpret_cast<const float4*>(vrow + i * 16);
            if (i == 0 && q == 0) x.x = 0.f;          // zero time coordinate
            svloc += x.x * x.x + x.y * x.y + x.z * x.z + x.w * x.w;
            __half h0 = __float2half_rn(x.x), h1 = __float2half_rn(x.y);
            __half h2 = __float2half_rn(x.z), h3 = __float2half_rn(x.w);
            char* dst = smc + i * 2048 + aStsOff;
            *reinterpret_cast<uint2*>(dst) =
                make_uint2(packh(h0, h1), packh(h2, h3));
        }
    }

    // ldmatrix lane offsets: A tile = 16 sub-tiles [rowgroup*2 + ktile]
    uint32_t aoff[4];
    {
        int m = lane >> 3;
        int tsel = ((m & 1) << 1) | (m >> 1);    // matrix -> tile {0,2,1,3}
        #pragma unroll
        for (int mt = 0; mt < 4; ++mt)
            aoff[mt] = (uint32_t)((mt * 4 + tsel) * 128 + (lane & 7) * 16);
    }
    const uint32_t boff = (uint32_t)((lane >> 3) * 128 + (lane & 7) * 16);

    // A tile visible to all warps (the ONLY CTA barrier before the epilogue)
    __syncthreads();

    float acc[4][4][4];
    #pragma unroll
    for (int mt = 0; mt < 4; ++mt)
        #pragma unroll
        for (int nt = 0; nt < 4; ++nt)
            #pragma unroll
            for (int e = 0; e < 4; ++e) acc[mt][nt][e] = 0.f;

    // ---- mainloop: warp-private pipeline, NO CTA barriers ----
    for (int i = 0; i < NCH; ++i) {
        if (i < NCH - 1) { CP_WAIT1(); } else { CP_WAIT0(); }   // chunk i done
        __syncwarp();                          // cross-lane visibility

        const uint32_t ab = smem0 + i * 2048;
        uint32_t ah[4][4];
        #pragma unroll
        for (int mt = 0; mt < 4; ++mt) LDSM4(ah[mt], ab + aoff[mt]);

        const uint32_t wb = smem0 + A_BYTES
                          + (uint32_t)(wid * 2 + (i & 1)) * WSTG_B + boff;
        #pragma unroll
        for (int nt = 0; nt < 4; ++nt) {
            uint32_t bq[4];
            LDSM4(bq, wb + nt * 512);
            #pragma unroll
            for (int mt = 0; mt < 4; ++mt) {
                MMAF16(acc[mt][nt], ah[mt], bq[0], bq[1]);   // hi*hi
                MMAF16(acc[mt][nt], ah[mt], bq[2], bq[3]);   // hi*lo
            }
        }

        // refill the stage just consumed (lead-2)
        if (i + 2 < NCH) cp_w(i + 2, i & 1);
    }
    __syncthreads();                   // all warps done; alias region reusable

    // ---- Sv + bias into alias region ----
    svloc += __shfl_xor_sync(~0u, svloc, 1);
    svloc += __shfl_xor_sync(~0u, svloc, 2);
    if (q == 0) svsum[lr] = svloc;
    {
        float bv = (tid == 0) ? 0.f : __ldg(&bias[tid - 1]);
        sbias[tid] = bv;
        float sq = bv * bv;
        #pragma unroll
        for (int o = 16; o > 0; o >>= 1) sq += __shfl_xor_sync(~0u, sq, o);
        if (lane == 0) sred[wid] = sq;
    }
    __syncthreads();
    if (tid == 0) {
        float s = 0.f;
        #pragma unroll
        for (int i = 0; i < 8; i++) s += sred[i];
        *sSb = s;
    }

    // per-thread partial Sg/dg over its 8 columns x 8 rows
    float psg[8], pdg[8];
    #pragma unroll
    for (int e = 0; e < 8; ++e) { psg[e] = 0.f; pdg[e] = 0.f; }
    const bool isc0 = (wn == 0 && (lane & 3) == 0);   // col0 owner when nt==0
    #pragma unroll
    for (int nt = 0; nt < 4; ++nt) {
        float2 bf = *reinterpret_cast<const float2*>(
            &sbias[wn * 32 + nt * 8 + 2 * (lane & 3)]);
        #pragma unroll
        for (int mt = 0; mt < 4; ++mt) {
            const float* C = acc[mt][nt];
            if (!(isc0 && nt == 0)) {             // exclude column 0
                psg[mt * 2]     = fmaf(C[0], C[0], psg[mt * 2]);
                pdg[mt * 2]     = fmaf(C[0], bf.x, pdg[mt * 2]);
                psg[mt * 2 + 1] = fmaf(C[2], C[2], psg[mt * 2 + 1]);
                pdg[mt * 2 + 1] = fmaf(C[2], bf.x, pdg[mt * 2 + 1]);
            }
            psg[mt * 2]     = fmaf(C[1], C[1], psg[mt * 2]);
            pdg[mt * 2]     = fmaf(C[1], bf.y, pdg[mt * 2]);
            psg[mt * 2 + 1] = fmaf(C[3], C[3], psg[mt * 2 + 1]);
            pdg[mt * 2 + 1] = fmaf(C[3], bf.y, pdg[mt * 2 + 1]);
        }
    }
    #pragma unroll
    for (int e = 0; e < 8; ++e) {
        psg[e] += __shfl_xor_sync(~0u, psg[e], 1);
        psg[e] += __shfl_xor_sync(~0u, psg[e], 2);
        pdg[e] += __shfl_xor_sync(~0u, pdg[e], 1);
        pdg[e] += __shfl_xor_sync(~0u, pdg[e], 2);
    }
    if ((lane & 3) == 0) {
        #pragma unroll
        for (int mt = 0; mt < 4; ++mt) {
            #pragma unroll
            for (int rp = 0; rp < 2; ++rp) {
                int r = mt * 16 + rp * 8 + (lane >> 2);
                sgp[r * 8 + wn]  = psg[mt * 2 + rp];
                sdgp[r * 8 + wn] = pdg[mt * 2 + rp];
            }
        }
    }
    __syncthreads();

    if (tid < 64) {
        float Sg = 0.f, dg = 0.f;
        #pragma unroll
        for (int e = 0; e < 8; ++e) { Sg += sgp[tid * 8 + e]; dg += sdgp[tid * 8 + e]; }

        const float c   = *cin_p;
        const float c2  = *cout_p;
        const float sqc = sqrtf(c);
        const float sq2 = sqrtf(c2);
        const float Sb  = *sSb;
        const float Sv  = svsum[tid];

        const float v0p  = sqrtf(c + Sv);
        const float m    = (sqc * acoshf(fmaxf(v0p / sqc - EPSF, ACOSH_MINF)))
                           / (sqrtf(Sv) + EPSF);
        const float Sw   = m * m * Sg;
        const float dw   = m * dg;
        const float n    = sqrtf(Sw) / sqc + EPSF;
        const float ncl  = fminf(n, CLIPF);
        const float ch   = coshf(ncl);
        const float sfac = sinhf(ncl) / n;
        const float T    = sfac * sfac * Sw;
        const float hp0  = sqrtf(c + T);
        const float dd   = sqc * acoshf(fmaxf(ch, ACOSH_MINF));
        const float d2   = sqc * acoshf(fmaxf(hp0 / sqc - EPSF, ACOSH_MINF));
        const float u0   = sqc - hp0 * hp0 / sqc;
        const float suj2 = (hp0 * hp0 / c) * T;
        const float nrmu = sqrtf(suj2 - u0 * u0);
        const float mlt  = d2 / (nrmu + EPSF);
        const float alph = 1.f - mlt * (hp0 / sqc) * sfac;
        const float m2   = dw / (dd * dd);
        const float beta = alph * m2;
        const float bt0  = -(mlt * u0) * m2;
        const float btsq = bt0 * bt0 + Sb - 2.f * beta * dw + beta * beta * Sw;
        const float nb   = sqrtf(btsq) / sqc + EPSF;
        const float nbcl = fminf(nb, CLIPF);
        const float chb  = coshf(nbcl);
        const float sfb  = sinhf(nbcl) / nb;
        const float gam  = chb * sfac - sfb * beta;
        const float del  = sfb;
        const float Sbi  = gam * gam * Sw + 2.f * gam * del * dw + del * del * Sb;
        const float p0   = sqrtf(c + Sbi);
        const float d3   = sqc * acoshf(fmaxf(p0 / sqc - EPSF, ACOSH_MINF));
        const float qn   = sqrtf(Sbi);
        const float mlt3 = d3 / (qn + EPSF);
        const float nf   = mlt3 * qn / sq2 + EPSF;
        const float nfcl = fminf(nf, CLIPF);
        const float phi  = (sinhf(nfcl) / nf) * mlt3;
        sAw[tid] = phi * gam * m;
        sAb[tid] = phi * del;
        sO0[tid] = sq2 * coshf(nfcl);
    }
    __syncthreads();

    // stores: each warp covers cols wn*32..+31 of all 64 rows
    #pragma unroll
    for (int mt = 0; mt < 4; ++mt) {
        #pragma unroll
        for (int rp = 0; rp < 2; ++rp) {
            int r = mt * 16 + rp * 8 + (lane >> 2);
            float Aw = sAw[r], Ab = sAb[r];
            float* orow = out + (size_t)(row0 + r) * D;
            #pragma unroll
            for (int nt = 0; nt < 4; ++nt) {
                float2 bf = *reinterpret_cast<const float2*>(
                    &sbias[wn * 32 + nt * 8 + 2 * (lane & 3)]);
                float g0 = acc[mt][nt][rp * 2];
                float g1 = acc[mt][nt][rp * 2 + 1];
                float2 o;
                o.x = fmaf(Aw, g0, Ab * bf.x);
                o.y = fmaf(Aw, g1, Ab * bf.y);
                if (wn == 0 && nt == 0 && (lane & 3) == 0) o.x = sO0[r];
                *reinterpret_cast<float2*>(
                    orow + wn * 32 + nt * 8 + 2 * (lane & 3)) = o;
            }
        }
    }
}

extern "C" void kernel_launch(void* const* d_in, const int* in_sizes, int n_in,
                              void* d_out, int out_size)
{
    const float* V    = (const float*)d_in[0];
    const float* cin  = (const float*)d_in[1];
    const float* cout = (const float*)d_in[2];
    const float* W    = (const float*)d_in[3];
    const float* bias = (const float*)d_in[4];
    float* out = (float*)d_out;

    const int nrow = in_sizes[0] / D;             // 131072

    cudaFuncSetAttribute(dh_mma, cudaFuncAttributeMaxDynamicSharedMemorySize,
                         SMEM_DYN);

    prep_w<<<32, 256>>>(W);
    dh_mma<<<nrow / BM, NT, SMEM_DYN>>>(V, cin, cout, bias, out);
}

// round 13
// speedup vs baseline: 1.8044x; 1.1540x over previous
#include <cuda_runtime.h>
#include <cuda_fp16.h>
#include <cstdint>
#include <math.h>

// DenseHyperbolic: fused GEMM (mma.sync m16n8k16, plain fp16 with fp32
// accumulate) + analytic hyperbolic epilogue.
//   g = v'(col0=0) @ W ; out_j = Aw*g_j + Ab*bias_j ; out_0 = sqrt(c2)*cosh(.)
//
// R12 hit the 2-term MMA floor (65us tensor-busy of 121us). R13 drops the
// b_lo term as well: plain fp16 GEMM. Calibrated error model: each dropped
// low term costs 1.6e-4 rel_err (measured in R10); two independent terms
// -> ~2.3e-4 total, 3-4x margin under the 1e-3 gate. Tensor work halves
// (32us floor), W image/copies/LDSM halve. Warp grid 1Mx8N, warp-private
// cp.async pipelines (no CTA barriers in the mainloop). 48KB/CTA, 2 CTAs/SM.

constexpr int D   = 256;
constexpr int BM  = 64;
constexpr int NCH = 16;            // chunks of K=16
constexpr int NT  = 256;
constexpr int A_BYTES = 32768;     // 16 chunks x 2KB (hi only)
constexpr int WSTG_B  = 1024;      // per warp per stage (32-col slice, hi only)
constexpr int SMEM_DYN = A_BYTES + 8 * 2 * WSTG_B;   // 48 KB

#define EPSF       1e-4f
#define ACOSH_MINF 1.0001f
#define CLIPF      8.0f

// W image (hi only): [16 chunks][32 ngroups][2 tiles: hiK0|hiK1][64 halves]
__device__ __half w_img[16 * 4096];

__device__ __forceinline__ uint32_t smem_u32(const void* p) {
    uint32_t a;
    asm("{ .reg .u64 t; cvta.to.shared.u64 t, %1; cvt.u32.u64 %0, t; }"
        : "=r"(a) : "l"(p));
    return a;
}
__device__ __forceinline__ uint32_t packh(__half a, __half b) {
    __half2 h = __halves2half2(a, b);
    return *reinterpret_cast<uint32_t*>(&h);
}

#define MMAF16(C, A, b0, b1) \
    asm volatile("mma.sync.aligned.m16n8k16.row.col.f32.f16.f16.f32 " \
        "{%0,%1,%2,%3}, {%4,%5,%6,%7}, {%8,%9}, {%0,%1,%2,%3};" \
        : "+f"((C)[0]), "+f"((C)[1]), "+f"((C)[2]), "+f"((C)[3]) \
        : "r"((A)[0]), "r"((A)[1]), "r"((A)[2]), "r"((A)[3]), \
          "r"(b0), "r"(b1))

#define LDSM4(R, addr) \
    asm volatile("ldmatrix.sync.aligned.m8n8.x4.shared.b16 {%0,%1,%2,%3}, [%4];" \
        : "=r"((R)[0]), "=r"((R)[1]), "=r"((R)[2]), "=r"((R)[3]) : "r"(addr))

#define CP_ASYNC16(dst_u32, src_ptr) \
    asm volatile("cp.async.cg.shared.global [%0], [%1], 16;" \
                 :: "r"(dst_u32), "l"(src_ptr))
#define CP_COMMIT() asm volatile("cp.async.commit_group;")
#define CP_WAIT0()  asm volatile("cp.async.wait_group 0;" ::: "memory")
#define CP_WAIT1()  asm volatile("cp.async.wait_group 1;" ::: "memory")

// ---- prep: W[k][n] row-major -> fragment-tiled fp16 (hi) image ----
__global__ void prep_w(const float* __restrict__ W) {
    int t = blockIdx.x * 256 + threadIdx.x;      // 8192 tasks
    int c  = t >> 9;                             // k16 chunk
    int rm = t & 511;
    int ng = rm >> 4;                            // n group (8 cols)
    int kt = (rm >> 3) & 1;
    int rr = rm & 7;                             // n within group
    int n  = ng * 8 + rr;
    int kb = c * 16 + kt * 8;
    __half h[8];
    #pragma unroll
    for (int j = 0; j < 8; ++j)
        h[j] = __float2half_rn(W[(size_t)(kb + j) * 256 + n]);
    size_t base = (size_t)c * 4096 + ng * 128 + kt * 64 + rr * 8;   // halves
    *reinterpret_cast<uint4*>(w_img + base) = *reinterpret_cast<const uint4*>(h);
}

// ---- main kernel ----
__global__ __launch_bounds__(NT, 2)
void dh_mma(const float* __restrict__ V,
            const float* __restrict__ cin_p,
            const float* __restrict__ cout_p,
            const float* __restrict__ bias,
            float* __restrict__ out)
{
    extern __shared__ __align__(16) char smc[];   // A 32KB | warp stages 16KB
    const int tid  = threadIdx.x;
    const int lane = tid & 31;
    const int wid  = tid >> 5;
    const int wn   = wid;             // 0..7 (N); warp tile = 64 rows x 32 cols
    const int row0 = blockIdx.x * BM;
    const uint32_t smem0 = smem_u32(smc);

    // epilogue alias region (inside warp-stage area; used only after mainloop)
    float* al     = reinterpret_cast<float*>(smc + A_BYTES);
    float* sbias  = al;               // 256
    float* sgp    = al + 256;         // 64 x 8
    float* sdgp   = al + 768;         // 64 x 8
    float* svsum  = al + 1280;        // 64
    float* sAw    = al + 1344;
    float* sAb    = al + 1408;
    float* sO0    = al + 1472;
    float* sred   = al + 1536;        // 8
    float* sSb    = al + 1544;

    // ---- warp-private W slice cp.async (1KB contiguous: ngroups wn*4..+3) --
    auto cp_w = [&](int i, int stg) {
        const __half* src = w_img + (size_t)i * 4096 + wn * 512;
        uint32_t dst = smem0 + A_BYTES + (uint32_t)(wid * 2 + stg) * WSTG_B;
        #pragma unroll
        for (int j = 0; j < 2; ++j) {
            int f = lane + j * 32;               // 16B units, 0..63
            CP_ASYNC16(dst + f * 16, src + f * 8);
        }
        CP_COMMIT();
    };

    // lead-2 prologue flies during the A conversion
    cp_w(0, 0);
    cp_w(1, 1);

    // ---- A prologue: convert 64x256 tile to hi fp16, resident in smem ----
    const int lr = tid >> 2;
    const int q  = tid & 3;
    const uint32_t aStsOff = (uint32_t)(((lr >> 3) * 2 + (q >> 1)) * 128
                                        + (lr & 7) * 16 + (q & 1) * 8);
    float svloc = 0.f;
    {
        const float* vrow = V + (size_t)(row0 + lr) * D + q * 4;
        #pragma unroll 4
        for (int i = 0; i < NCH; ++i) {
            float4 x = *reinterpret_cast<const float4*>(vrow + i * 16);
            if (i == 0 && q == 0) x.x = 0.f;          // zero time coordinate
            svloc += x.x * x.x + x.y * x.y + x.z * x.z + x.w * x.w;
            __half h0 = __float2half_rn(x.x), h1 = __float2half_rn(x.y);
            __half h2 = __float2half_rn(x.z), h3 = __float2half_rn(x.w);
            char* dst = smc + i * 2048 + aStsOff;
            *reinterpret_cast<uint2*>(dst) =
                make_uint2(packh(h0, h1), packh(h2, h3));
        }
    }

    // ldmatrix lane offsets: A tile = 16 sub-tiles [rowgroup*2 + ktile]
    uint32_t aoff[4];
    {
        int m = lane >> 3;
        int tsel = ((m & 1) << 1) | (m >> 1);    // matrix -> tile {0,2,1,3}
        #pragma unroll
        for (int mt = 0; mt < 4; ++mt)
            aoff[mt] = (uint32_t)((mt * 4 + tsel) * 128 + (lane & 7) * 16);
    }
    // B: tiles in memory order [ng0kt0, ng0kt1, ng1kt0, ng1kt1, ...]; one
    // LDSM4 covers 2 ngroups x 2 ktiles (matrix m = tile m).
    const uint32_t boff = (uint32_t)((lane >> 3) * 128 + (lane & 7) * 16);

    // A tile visible to all warps (the ONLY CTA barrier before the epilogue)
    __syncthreads();

    float acc[4][4][4];
    #pragma unroll
    for (int mt = 0; mt < 4; ++mt)
        #pragma unroll
        for (int nt = 0; nt < 4; ++nt)
            #pragma unroll
            for (int e = 0; e < 4; ++e) acc[mt][nt][e] = 0.f;

    // ---- mainloop: warp-private pipeline, NO CTA barriers ----
    for (int i = 0; i < NCH; ++i) {
        if (i < NCH - 1) { CP_WAIT1(); } else { CP_WAIT0(); }   // chunk i done
        __syncwarp();                          // cross-lane visibility

        const uint32_t ab = smem0 + i * 2048;
        uint32_t ah[4][4];
        #pragma unroll
        for (int mt = 0; mt < 4; ++mt) LDSM4(ah[mt], ab + aoff[mt]);

        const uint32_t wb = smem0 + A_BYTES
                          + (uint32_t)(wid * 2 + (i & 1)) * WSTG_B + boff;
        #pragma unroll
        for (int np = 0; np < 2; ++np) {       // ngroup pairs
            uint32_t bq[4];
            LDSM4(bq, wb + np * 512);
            #pragma unroll
            for (int mt = 0; mt < 4; ++mt) {
                MMAF16(acc[mt][np * 2],     ah[mt], bq[0], bq[1]);
                MMAF16(acc[mt][np * 2 + 1], ah[mt], bq[2], bq[3]);
            }
        }

        // refill the stage just consumed (lead-2)
        if (i + 2 < NCH) cp_w(i + 2, i & 1);
    }
    __syncthreads();                   // all warps done; alias region reusable

    // ---- Sv + bias into alias region ----
    svloc += __shfl_xor_sync(~0u, svloc, 1);
    svloc += __shfl_xor_sync(~0u, svloc, 2);
    if (q == 0) svsum[lr] = svloc;
    {
        float bv = (tid == 0) ? 0.f : __ldg(&bias[tid - 1]);
        sbias[tid] = bv;
        float sq = bv * bv;
        #pragma unroll
        for (int o = 16; o > 0; o >>= 1) sq += __shfl_xor_sync(~0u, sq, o);
        if (lane == 0) sred[wid] = sq;
    }
    __syncthreads();
    if (tid == 0) {
        float s = 0.f;
        #pragma unroll
        for (int i = 0; i < 8; i++) s += sred[i];
        *sSb = s;
    }

    // per-thread partial Sg/dg over its 8 columns x 8 rows
    float psg[8], pdg[8];
    #pragma unroll
    for (int e = 0; e < 8; ++e) { psg[e] = 0.f; pdg[e] = 0.f; }
    const bool isc0 = (wn == 0 && (lane & 3) == 0);   // col0 owner when nt==0
    #pragma unroll
    for (int nt = 0; nt < 4; ++nt) {
        float2 bf = *reinterpret_cast<const float2*>(
            &sbias[wn * 32 + nt * 8 + 2 * (lane & 3)]);
        #pragma unroll
        for (int mt = 0; mt < 4; ++mt) {
            const float* C = acc[mt][nt];
            if (!(isc0 && nt == 0)) {             // exclude column 0
                psg[mt * 2]     = fmaf(C[0], C[0], psg[mt * 2]);
                pdg[mt * 2]     = fmaf(C[0], bf.x, pdg[mt * 2]);
                psg[mt * 2 + 1] = fmaf(C[2], C[2], psg[mt * 2 + 1]);
                pdg[mt * 2 + 1] = fmaf(C[2], bf.x, pdg[mt * 2 + 1]);
            }
            psg[mt * 2]     = fmaf(C[1], C[1], psg[mt * 2]);
            pdg[mt * 2]     = fmaf(C[1], bf.y, pdg[mt * 2]);
            psg[mt * 2 + 1] = fmaf(C[3], C[3], psg[mt * 2 + 1]);
            pdg[mt * 2 + 1] = fmaf(C[3], bf.y, pdg[mt * 2 + 1]);
        }
    }
    #pragma unroll
    for (int e = 0; e < 8; ++e) {
        psg[e] += __shfl_xor_sync(~0u, psg[e], 1);
        psg[e] += __shfl_xor_sync(~0u, psg[e], 2);
        pdg[e] += __shfl_xor_sync(~0u, pdg[e], 1);
        pdg[e] += __shfl_xor_sync(~0u, pdg[e], 2);
    }
    if ((lane & 3) == 0) {
        #pragma unroll
        for (int mt = 0; mt < 4; ++mt) {
            #pragma unroll
            for (int rp = 0; rp < 2; ++rp) {
                int r = mt * 16 + rp * 8 + (lane >> 2);
                sgp[r * 8 + wn]  = psg[mt * 2 + rp];
                sdgp[r * 8 + wn] = pdg[mt * 2 + rp];
            }
        }
    }
    __syncthreads();

    if (tid < 64) {
        float Sg = 0.f, dg = 0.f;
        #pragma unroll
        for (int e = 0; e < 8; ++e) { Sg += sgp[tid * 8 + e]; dg += sdgp[tid * 8 + e]; }

        const float c   = *cin_p;
        const float c2  = *cout_p;
        const float sqc = sqrtf(c);
        const float sq2 = sqrtf(c2);
        const float Sb  = *sSb;
        const float Sv  = svsum[tid];

        const float v0p  = sqrtf(c + Sv);
        const float m    = (sqc * acoshf(fmaxf(v0p / sqc - EPSF, ACOSH_MINF)))
                           / (sqrtf(Sv) + EPSF);
        const float Sw   = m * m * Sg;
        const float dw   = m * dg;
        const float n    = sqrtf(Sw) / sqc + EPSF;
        const float ncl  = fminf(n, CLIPF);
        const float ch   = coshf(ncl);
        const float sfac = sinhf(ncl) / n;
        const float T    = sfac * sfac * Sw;
        const float hp0  = sqrtf(c + T);
        const float dd   = sqc * acoshf(fmaxf(ch, ACOSH_MINF));
        const float d2   = sqc * acoshf(fmaxf(hp0 / sqc - EPSF, ACOSH_MINF));
        const float u0   = sqc - hp0 * hp0 / sqc;
        const float suj2 = (hp0 * hp0 / c) * T;
        const float nrmu = sqrtf(suj2 - u0 * u0);
        const float mlt  = d2 / (nrmu + EPSF);
        const float alph = 1.f - mlt * (hp0 / sqc) * sfac;
        const float m2   = dw / (dd * dd);
        const float beta = alph * m2;
        const float bt0  = -(mlt * u0) * m2;
        const float btsq = bt0 * bt0 + Sb - 2.f * beta * dw + beta * beta * Sw;
        const float nb   = sqrtf(btsq) / sqc + EPSF;
        const float nbcl = fminf(nb, CLIPF);
        const float chb  = coshf(nbcl);
        const float sfb  = sinhf(nbcl) / nb;
        const float gam  = chb * sfac - sfb * beta;
        const float del  = sfb;
        const float Sbi  = gam * gam * Sw + 2.f * gam * del * dw + del * del * Sb;
        const float p0   = sqrtf(c + Sbi);
        const float d3   = sqc * acoshf(fmaxf(p0 / sqc - EPSF, ACOSH_MINF));
        const float qn   = sqrtf(Sbi);
        const float mlt3 = d3 / (qn + EPSF);
        const float nf   = mlt3 * qn / sq2 + EPSF;
        const float nfcl = fminf(nf, CLIPF);
        const float phi  = (sinhf(nfcl) / nf) * mlt3;
        sAw[tid] = phi * gam * m;
        sAb[tid] = phi * del;
        sO0[tid] = sq2 * coshf(nfcl);
    }
    __syncthreads();

    // stores: each warp covers cols wn*32..+31 of all 64 rows
    #pragma unroll
    for (int mt = 0; mt < 4; ++mt) {
        #pragma unroll
        for (int rp = 0; rp < 2; ++rp) {
            int r = mt * 16 + rp * 8 + (lane >> 2);
            float Aw = sAw[r], Ab = sAb[r];
            float* orow = out + (size_t)(row0 + r) * D;
            #pragma unroll
            for (int nt = 0; nt < 4; ++nt) {
                float2 bf = *reinterpret_cast<const float2*>(
                    &sbias[wn * 32 + nt * 8 + 2 * (lane & 3)]);
                float g0 = acc[mt][nt][rp * 2];
                float g1 = acc[mt][nt][rp * 2 + 1];
                float2 o;
                o.x = fmaf(Aw, g0, Ab * bf.x);
                o.y = fmaf(Aw, g1, Ab * bf.y);
                if (wn == 0 && nt == 0 && (lane & 3) == 0) o.x = sO0[r];
                *reinterpret_cast<float2*>(
                    orow + wn * 32 + nt * 8 + 2 * (lane & 3)) = o;
            }
        }
    }
}

extern "C" void kernel_launch(void* const* d_in, const int* in_sizes, int n_in,
                              void* d_out, int out_size)
{
    const float* V    = (const float*)d_in[0];
    const float* cin  = (const float*)d_in[1];
    const float* cout = (const float*)d_in[2];
    const float* W    = (const float*)d_in[3];
    const float* bias = (const float*)d_in[4];
    float* out = (float*)d_out;

    const int nrow = in_sizes[0] / D;             // 131072

    cudaFuncSetAttribute(dh_mma, cudaFuncAttributeMaxDynamicSharedMemorySize,
                         SMEM_DYN);

    prep_w<<<32, 256>>>(W);
    dh_mma<<<nrow / BM, NT, SMEM_DYN>>>(V, cin, cout, bias, out);
}